// round 2
// baseline (speedup 1.0000x reference)
#include <cuda_runtime.h>
#include <cuda_bf16.h>

#define BB 32
#define TT 1000
#define EE 512
#define DD 1024
#define AA 512
#define CC 10
#define FF 100
#define KW 201
#define ODIM_ 5000
#define LL 100
#define OLEN 101
#define SOS_ 4998
#define NROW 4096
#define KCAT 2560
#define MOUT 3232
#define MOUT_PAD 3328

__device__ float g_pre[BB * TT * AA];
__device__ float g_wcat[NROW * KCAT];
__device__ float g_bcat[NROW];
__device__ float g_aw[BB * TT];
__device__ float g_e[BB * TT];
__device__ float g_conv[BB * CC * TT];
__device__ float g_dec[BB * AA];
__device__ float g_ctxp[4 * BB * EE];
__device__ float g_z[2][BB * DD];
__device__ float g_c[BB * DD];
__device__ float g_zall[MOUT_PAD * DD];

__device__ __forceinline__ float tanh_fast(float x) {
    float y;
    asm("tanh.approx.f32 %0, %1;" : "=f"(y) : "f"(x));
    return y;
}

__global__ void k_init() {
    int i = blockIdx.x * blockDim.x + threadIdx.x;
    if (i < BB * DD) { g_z[0][i] = 0.f; g_c[i] = 0.f; }
    if (i < BB * TT) g_aw[i] = 1.0f / TT;
}

__global__ void k_wcat(const float* __restrict__ w_ih, const float* __restrict__ w_hh,
                       const float* __restrict__ b_ih, const float* __restrict__ b_hh) {
    int i = blockIdx.x * blockDim.x + threadIdx.x;
    if (i < NROW * KCAT) {
        int r = i / KCAT, k = i - r * KCAT;
        int n = (r & 3) * DD + (r >> 2);
        g_wcat[i] = (k < DD + EE) ? w_ih[n * (DD + EE) + k] : w_hh[n * DD + (k - (DD + EE))];
    }
    if (i < NROW) {
        int n = (i & 3) * DD + (i >> 2);
        g_bcat[i] = b_ih[n] + b_hh[n];
    }
}

// C = A[MxK] * B[NxK]^T + bias. MODE 0: pre (C=g_pre). MODE 1: out (scatter to d_out).
template <int MODE>
__global__ __launch_bounds__(256) void k_sgemm(const float* __restrict__ Aarg,
                                               const float* __restrict__ Bm,
                                               const float* __restrict__ bias,
                                               float* __restrict__ Cout,
                                               int N, int K) {
    __shared__ float As[16][132];
    __shared__ float Bs[16][132];
    const float* A = (MODE == 1) ? g_zall : Aarg;
    int tid = threadIdx.x;
    int m0 = blockIdx.y * 128, n0 = blockIdx.x * 128;
    float acc[8][8];
#pragma unroll
    for (int i = 0; i < 8; i++)
#pragma unroll
        for (int j = 0; j < 8; j++) acc[i][j] = 0.f;
    int tm0 = (tid >> 4) << 3, tn0 = (tid & 15) << 3;
    for (int k0 = 0; k0 < K; k0 += 16) {
#pragma unroll
        for (int i = 0; i < 2; i++) {
            int lin = tid + (i << 8);
            int row = lin >> 2, kq = (lin & 3) << 2;
            float4 va = *(const float4*)(A + (size_t)(m0 + row) * K + k0 + kq);
            As[kq + 0][row] = va.x; As[kq + 1][row] = va.y;
            As[kq + 2][row] = va.z; As[kq + 3][row] = va.w;
            int nr = n0 + row;
            float4 vb = make_float4(0.f, 0.f, 0.f, 0.f);
            if (MODE == 0 || nr < N) vb = *(const float4*)(Bm + (size_t)nr * K + k0 + kq);
            Bs[kq + 0][row] = vb.x; Bs[kq + 1][row] = vb.y;
            Bs[kq + 2][row] = vb.z; Bs[kq + 3][row] = vb.w;
        }
        __syncthreads();
#pragma unroll
        for (int kk = 0; kk < 16; kk++) {
            float a[8], b[8];
            *(float4*)&a[0] = *(const float4*)&As[kk][tm0];
            *(float4*)&a[4] = *(const float4*)&As[kk][tm0 + 4];
            *(float4*)&b[0] = *(const float4*)&Bs[kk][tn0];
            *(float4*)&b[4] = *(const float4*)&Bs[kk][tn0 + 4];
#pragma unroll
            for (int i = 0; i < 8; i++)
#pragma unroll
                for (int j = 0; j < 8; j++)
                    acc[i][j] = fmaf(a[i], b[j], acc[i][j]);
        }
        __syncthreads();
    }
#pragma unroll
    for (int i = 0; i < 8; i++) {
        int m_ = m0 + tm0 + i;
#pragma unroll
        for (int j = 0; j < 8; j++) {
            int n_ = n0 + tn0 + j;
            if (MODE == 1 && n_ >= N) continue;
            float v = acc[i][j] + bias[n_];
            if (MODE == 1) {
                if (m_ < MOUT) {
                    int b_ = m_ & 31, o_ = m_ >> 5;
                    Cout[(size_t)(b_ * OLEN + o_) * ODIM_ + n_] = v;
                }
            } else {
                g_pre[(size_t)m_ * N + n_] = v;
            }
        }
    }
}

__global__ __launch_bounds__(256) void k_small(const float* __restrict__ w_dec,
                                               const float* __restrict__ w_conv, int step) {
    __shared__ float sm[1408];
    int blk = blockIdx.x, tid = threadIdx.x;
    if (blk < BB * CC) {
        int b = blk / CC, c = blk - b * CC;
        float* aw_s = sm;
        float* wk = sm + 1200;
        for (int i = tid; i < TT + 2 * FF; i += 256)
            aw_s[i] = (i >= FF && i < FF + TT) ? g_aw[b * TT + i - FF] : 0.f;
        for (int i = tid; i < KW; i += 256) wk[i] = w_conv[c * KW + i];
        __syncthreads();
        for (int t = tid; t < TT; t += 256) {
            float s = 0.f;
#pragma unroll 4
            for (int k = 0; k < KW; k++) s = fmaf(wk[k], aw_s[t + k], s);
            g_conv[(b * CC + c) * TT + t] = s;
        }
    } else {
        int warp = tid >> 5, lane = tid & 31;
        int o0 = (blk - BB * CC) * 32 + warp * 4;
        int b = o0 >> 9, a0 = o0 & (AA - 1);
        const float* zp = g_z[step & 1] + b * DD;
        float s0 = 0.f, s1 = 0.f, s2 = 0.f, s3 = 0.f;
        for (int k = lane * 4; k < DD; k += 128) {
            float4 zv = *(const float4*)(zp + k);
            float4 w0 = *(const float4*)(w_dec + (size_t)(a0 + 0) * DD + k);
            float4 w1 = *(const float4*)(w_dec + (size_t)(a0 + 1) * DD + k);
            float4 w2 = *(const float4*)(w_dec + (size_t)(a0 + 2) * DD + k);
            float4 w3 = *(const float4*)(w_dec + (size_t)(a0 + 3) * DD + k);
            s0 += zv.x * w0.x + zv.y * w0.y + zv.z * w0.z + zv.w * w0.w;
            s1 += zv.x * w1.x + zv.y * w1.y + zv.z * w1.z + zv.w * w1.w;
            s2 += zv.x * w2.x + zv.y * w2.y + zv.z * w2.z + zv.w * w2.w;
            s3 += zv.x * w3.x + zv.y * w3.y + zv.z * w3.z + zv.w * w3.w;
        }
#pragma unroll
        for (int s = 16; s; s >>= 1) {
            s0 += __shfl_xor_sync(0xffffffffu, s0, s);
            s1 += __shfl_xor_sync(0xffffffffu, s1, s);
            s2 += __shfl_xor_sync(0xffffffffu, s2, s);
            s3 += __shfl_xor_sync(0xffffffffu, s3, s);
        }
        if (lane == 0) {
            g_dec[b * AA + a0 + 0] = s0;
            g_dec[b * AA + a0 + 1] = s1;
            g_dec[b * AA + a0 + 2] = s2;
            g_dec[b * AA + a0 + 3] = s3;
        }
    }
}

__global__ __launch_bounds__(128) void k_e(const float* __restrict__ w_att,
                                           const float* __restrict__ w_gvec) {
    int b = blockIdx.y, t0 = blockIdx.x * 40;
    int tid = threadIdx.x;
    __shared__ float conv_s[40][10];
    __shared__ float part_s[40][4];
    for (int i = tid; i < 400; i += 128) {
        int c = i / 40, tl = i - c * 40;
        conv_s[tl][c] = g_conv[(b * CC + c) * TT + t0 + tl];
    }
    int a0 = tid * 4;
    float wr[4][10], gg[4], dc[4];
#pragma unroll
    for (int j = 0; j < 4; j++) {
#pragma unroll
        for (int c = 0; c < 10; c++) wr[j][c] = w_att[(a0 + j) * CC + c];
        gg[j] = w_gvec[a0 + j];
        dc[j] = g_dec[b * AA + a0 + j];
    }
    __syncthreads();
    int lane = tid & 31, warp = tid >> 5;
    const float* prep = g_pre + (size_t)b * TT * AA + (size_t)t0 * AA + a0;
    for (int tl = 0; tl < 40; tl++) {
        float4 p = *(const float4*)(prep + (size_t)tl * AA);
        float pa[4] = {p.x, p.y, p.z, p.w};
        float acc = 0.f;
#pragma unroll
        for (int j = 0; j < 4; j++) {
            float x = pa[j] + dc[j];
#pragma unroll
            for (int c = 0; c < 10; c++) x = fmaf(conv_s[tl][c], wr[j][c], x);
            acc = fmaf(gg[j], tanh_fast(x), acc);
        }
#pragma unroll
        for (int s = 16; s; s >>= 1) acc += __shfl_xor_sync(0xffffffffu, acc, s);
        if (lane == 0) part_s[tl][warp] = acc;
    }
    __syncthreads();
    if (tid < 40)
        g_e[b * TT + t0 + tid] =
            part_s[tid][0] + part_s[tid][1] + part_s[tid][2] + part_s[tid][3];
}

__global__ __launch_bounds__(128) void k_ctx(const float* __restrict__ hpad) {
    int b = blockIdx.y;
    int ec = blockIdx.x & 3, tc = blockIdx.x >> 2;
    int tid = threadIdx.x;
    __shared__ float red[128];
    const float* ep = g_e + b * TT;
    float m = -1e30f;
    for (int t = tid; t < TT; t += 128) m = fmaxf(m, ep[t]);
    red[tid] = m; __syncthreads();
    for (int s = 64; s; s >>= 1) {
        if (tid < s) red[tid] = fmaxf(red[tid], red[tid + s]);
        __syncthreads();
    }
    float mx = red[0]; __syncthreads();
    float sm = 0.f;
    for (int t = tid; t < TT; t += 128) sm += __expf(2.f * (ep[t] - mx));
    red[tid] = sm; __syncthreads();
    for (int s = 64; s; s >>= 1) {
        if (tid < s) red[tid] += red[tid + s];
        __syncthreads();
    }
    float inv = 1.f / red[0];
    int e0 = ec * 128;
    int tstart = tc * 250;
    float acc = 0.f;
    const float* hp = hpad + (size_t)b * TT * EE + e0 + tid;
    for (int t = tstart; t < tstart + 250; t++) {
        float w = __expf(2.f * (ep[t] - mx)) * inv;
        acc = fmaf(w, hp[(size_t)t * EE], acc);
    }
    g_ctxp[(size_t)(tc * BB + b) * EE + e0 + tid] = acc;
    if (ec == 0)
        for (int t = tstart + tid; t < tstart + 250; t += 128)
            g_aw[b * TT + t] = __expf(2.f * (ep[t] - mx)) * inv;
}

__global__ __launch_bounds__(256) void k_lstm(const int* __restrict__ ys,
                                              const float* __restrict__ embed, int step) {
    __shared__ float ws[32][68];
    __shared__ float xs[64][36];
    __shared__ float gates_s[32][32];
    __shared__ int tok_s[32];
    int tid = threadIdx.x;
    int r0 = blockIdx.x * 32;
    if (tid < 32) tok_s[tid] = (step == 0) ? SOS_ : ys[tid * LL + step - 1];
    __syncthreads();
    int zr = step & 1;
    float acc0 = 0.f, acc1 = 0.f, acc2 = 0.f, acc3 = 0.f;
    int rl = tid >> 3, b0 = (tid & 7) << 2;
    int bb = tid >> 3, kk0 = tid & 7;
    for (int k0 = 0; k0 < KCAT; k0 += 64) {
#pragma unroll
        for (int i = 0; i < 2; i++) {
            int lin = tid + (i << 8);
            int row = lin >> 4, kq = (lin & 15) << 2;
            float4 w4 = *(const float4*)(g_wcat + (size_t)(r0 + row) * KCAT + k0 + kq);
            ws[row][kq + 0] = w4.x; ws[row][kq + 1] = w4.y;
            ws[row][kq + 2] = w4.z; ws[row][kq + 3] = w4.w;
        }
#pragma unroll
        for (int j = 0; j < 8; j++) {
            int kk = kk0 + (j << 3);
            int k = k0 + kk;
            float v;
            if (k < DD) v = embed[(size_t)tok_s[bb] * DD + k];
            else if (k < DD + EE) {
                int ei = bb * EE + (k - DD);
                v = g_ctxp[ei] + g_ctxp[BB * EE + ei] + g_ctxp[2 * BB * EE + ei] +
                    g_ctxp[3 * BB * EE + ei];
            } else v = g_z[zr][bb * DD + (k - DD - EE)];
            xs[kk][bb] = v;
        }
        __syncthreads();
#pragma unroll
        for (int kk = 0; kk < 64; kk++) {
            float w = ws[rl][kk];
            float4 x = *(const float4*)&xs[kk][b0];
            acc0 = fmaf(w, x.x, acc0); acc1 = fmaf(w, x.y, acc1);
            acc2 = fmaf(w, x.z, acc2); acc3 = fmaf(w, x.w, acc3);
        }
        __syncthreads();
    }
    float bias = g_bcat[r0 + rl];
    gates_s[rl][b0 + 0] = acc0 + bias;
    gates_s[rl][b0 + 1] = acc1 + bias;
    gates_s[rl][b0 + 2] = acc2 + bias;
    gates_s[rl][b0 + 3] = acc3 + bias;
    __syncthreads();
    int dl = tid >> 5, b = tid & 31;
    int d = (r0 >> 2) + dl;
    float iv = gates_s[dl * 4 + 0][b];
    float fv = gates_s[dl * 4 + 1][b];
    float gv = gates_s[dl * 4 + 2][b];
    float ov = gates_s[dl * 4 + 3][b];
    float si = 1.f / (1.f + expf(-iv));
    float sf = 1.f / (1.f + expf(-fv));
    float so = 1.f / (1.f + expf(-ov));
    float cn = sf * g_c[b * DD + d] + si * tanhf(gv);
    float zn = so * tanhf(cn);
    g_c[b * DD + d] = cn;
    g_z[zr ^ 1][b * DD + d] = zn;
    g_zall[(size_t)(step * BB + b) * DD + d] = zn;
}

extern "C" void kernel_launch(void* const* d_in, const int* in_sizes, int n_in,
                              void* d_out, int out_size) {
    const float* hpad   = (const float*)d_in[0];
    const int*   ys     = (const int*)d_in[1];
    const float* w_enc  = (const float*)d_in[2];
    const float* b_enc  = (const float*)d_in[3];
    const float* w_dec  = (const float*)d_in[4];
    const float* w_att  = (const float*)d_in[5];
    const float* w_conv = (const float*)d_in[6];
    const float* w_gvec = (const float*)d_in[7];
    const float* embed  = (const float*)d_in[9];
    const float* w_ih   = (const float*)d_in[10];
    const float* w_hh   = (const float*)d_in[11];
    const float* b_ih   = (const float*)d_in[12];
    const float* b_hh   = (const float*)d_in[13];
    const float* w_out  = (const float*)d_in[14];
    const float* b_out  = (const float*)d_in[15];
    float* out = (float*)d_out;

    k_init<<<128, 256>>>();
    k_wcat<<<(NROW * KCAT + 255) / 256, 256>>>(w_ih, w_hh, b_ih, b_hh);
    k_sgemm<0><<<dim3(4, 250), 256>>>(hpad, w_enc, b_enc, nullptr, 512, 512);

    for (int step = 0; step < OLEN; step++) {
        k_small<<<BB * CC + (BB * AA) / 32, 256>>>(w_dec, w_conv, step);
        k_e<<<dim3(25, BB), 128>>>(w_att, w_gvec);
        k_ctx<<<dim3(16, BB), 128>>>(hpad);
        k_lstm<<<NROW / 32, 256>>>(ys, embed, step);
    }
    k_sgemm<1><<<dim3(40, 26), 256>>>(nullptr, w_out, b_out, out, ODIM_, DD);
}